// round 15
// baseline (speedup 1.0000x reference)
#include <cuda_runtime.h>
#include <math.h>

// RealNVP backward_xz + log-density sum — round 14.
// BINS=32, E-table. Bins fitted on their true selection interval [k,k+1]
// (index constant 15.5) with midpoint equioscillation correction.
// Apply: mask-free fast path (track running max|z| only) + exact per-warp
// masked redo fallback (fires only if a lane would die — expected never).

#define N_SAMPLES 131072
#define NBLOCKS   32
#define HDIM      64
#define LIMIT_R   10.0f
#define BINS      32
#define SEG_BINS  8                       // bins per build CTA
#define BIN_W     (20.0f / 32.0f)         // 0.625, exact fp32
#define INV_BIN   1.6f
#define IDX_OFF   15.5f                   // tt2 = z*1.6 + 15.5; round -> bin
#define NCTA      128                     // <= 148 SMs: all wave-1 resident
#define TPB       1024
#define SMEM_BYTES 18432
#define MAGIC     12582912.0f             // 1.5 * 2^23

__device__ float4 g_bins[NBLOCKS * BINS];
__device__ float  g_partials[NCTA];
__device__ unsigned int g_build_done = 0; // reset by last CTA each run
__device__ unsigned int g_count = 0;      // reset by last CTA each run

struct BuildSmem {
    float  sW2[HDIM * HDIM];
    float2 sw1b1[HDIM];                   // (w1_i, b1_i)
    float2 sW3[HDIM];                     // row j: (shift_w_j, scale_w_j)
    float  sb2[HDIM];
    float2 sb3s;
    float2 snA[SEG_BINS + 1];             // (shift, E) at nodes u = U, U+1, ...
    float2 snB[SEG_BINS];                 // (shift, E) at midpoints u = U+0.5
};

extern __shared__ char smem_raw[];

__device__ __forceinline__ float warp_sum(float v) {
    #pragma unroll
    for (int off = 16; off > 0; off >>= 1)
        v += __shfl_xor_sync(0xffffffffu, v, off);
    return v;
}

__global__ __launch_bounds__(TPB) void realnvp_fused(
    const float* __restrict__ x,
    const float* __restrict__ W1, const float* __restrict__ b1,
    const float* __restrict__ W2, const float* __restrict__ b2,
    const float* __restrict__ W3, const float* __restrict__ b3,
    const float* __restrict__ loc, const float* __restrict__ logs,
    float* __restrict__ out)
{
    BuildSmem* bs = (BuildSmem*)smem_raw;     // phase-1 view (~17.5 KB)
    float4* sbins = (float4*)smem_raw;        // phase-2 view (16 KB), overlaid

    __shared__ float swarp[32];
    __shared__ bool  isLast;

    const int tid  = threadIdx.x;
    const int cta  = blockIdx.x;
    const int wid  = tid >> 5;
    const int lane = tid & 31;
    const int blk  = cta >> 2;                // flow block 0..31
    const int seg  = cta & 3;                 // 8-bin segment 0..3

    // ---- issue sample + param loads NOW; consumed after the barrier ----
    const int n = cta * TPB + tid;
    float2 xa = ((const float2*)x)[n];
    const float loc0 = loc[0],  loc1 = loc[1];
    const float ls0  = logs[0], ls1  = logs[1];

    // ================= phase 1: build this CTA's 8 bins =================
    {
        const float4* W2v = (const float4*)(W2 + blk * HDIM * HDIM);
        ((float4*)bs->sW2)[tid] = W2v[tid];   // 1024 float4 = whole W2

        if (tid < HDIM) {
            bs->sw1b1[tid] = make_float2(W1[blk * HDIM + tid], b1[blk * HDIM + tid]);
            bs->sb2[tid]   = b2[blk * HDIM + tid];
            bs->sW3[tid]   = ((const float2*)W3)[blk * HDIM + tid];
        }
        if (tid == 0) bs->sb3s = ((const float2*)b3)[blk];
    }
    __syncthreads();

    const float2 b3v = bs->sb3s;

    // warps 0..8: nodes u = seg*8 + w; warps 16..23: midpoints u + 0.5.
    // lane l owns hidden outputs 2l,2l+1; h1 broadcast by shuffle.
    const bool doNode = (wid <= SEG_BINS);
    const bool doMid  = (wid >= 16) && (wid < 16 + SEG_BINS);
    if (doNode || doMid) {
        const float u = doNode ? (float)(seg * SEG_BINS + wid)
                               : (float)(seg * SEG_BINS + (wid - 16)) + 0.5f;
        const float z = fmaf(u, BIN_W, -LIMIT_R);

        float2 wba = bs->sw1b1[lane];
        float2 wbb = bs->sw1b1[lane + 32];
        float hia = fmaxf(fmaf(z, wba.x, wba.y), 0.0f);   // h1[lane]
        float hib = fmaxf(fmaf(z, wbb.x, wbb.y), 0.0f);   // h1[lane+32]

        float acc0 = bs->sb2[2 * lane + 0];
        float acc1 = bs->sb2[2 * lane + 1];

        const float2* w2p = (const float2*)(bs->sW2) + lane;
        #pragma unroll
        for (int i = 0; i < 32; i++) {
            float hi = __shfl_sync(0xffffffffu, hia, i);
            float2 w2 = w2p[i * 32];
            acc0 = fmaf(hi, w2.x, acc0);
            acc1 = fmaf(hi, w2.y, acc1);
        }
        #pragma unroll
        for (int i = 0; i < 32; i++) {
            float hi = __shfl_sync(0xffffffffu, hib, i);
            float2 w2 = w2p[(i + 32) * 32];
            acc0 = fmaf(hi, w2.x, acc0);
            acc1 = fmaf(hi, w2.y, acc1);
        }

        float h0 = fmaxf(acc0, 0.0f);
        float h1 = fmaxf(acc1, 0.0f);
        float2 wa = bs->sW3[2 * lane + 0];
        float2 wb = bs->sW3[2 * lane + 1];
        float p0 = fmaf(h1, wb.x, h0 * wa.x);
        float p1 = fmaf(h1, wb.y, h0 * wa.y);

        p0 = warp_sum(p0);
        p1 = warp_sum(p1);
        if (lane == 0) {
            float2 v = make_float2(p0 + b3v.x, expf(-(p1 + b3v.y)));
            if (doNode) bs->snA[wid] = v;
            else        bs->snB[wid - 16] = v;
        }
    }
    __syncthreads();

    // bins: line through interval endpoints, intercept lowered by half the
    // chord-vs-midpoint gap (equioscillation: error centered, halved).
    // Evaluated at tt2 = u - 0.5, so fold the +0.5 shift into the intercept.
    if (tid < SEG_BINS) {
        float2 a = bs->snA[tid];
        float2 c = bs->snA[tid + 1];
        float2 m = bs->snB[tid];
        float U  = (float)(seg * SEG_BINS + tid);
        float sx = c.x - a.x, sE = c.y - a.y;
        float dx = 0.5f * (a.x + c.x) - m.x;   // chord - function at midpoint
        float dE = 0.5f * (a.y + c.y) - m.y;
        float ix = a.x + sx * (0.5f - U) - 0.5f * dx;
        float iE = a.y + sE * (0.5f - U) - 0.5f * dE;
        g_bins[blk * BINS + seg * SEG_BINS + tid] = make_float4(sx, ix, sE, iE);
    }
    __threadfence();          // publish bins before counting
    __syncthreads();

    if (tid == 0) {
        atomicAdd(&g_build_done, 1u);
        while (*(volatile unsigned int*)&g_build_done < NCTA)
            __nanosleep(32);
    }
    __syncthreads();
    __threadfence();          // acquire before reading peer bins

    // ============ phase 2: stage full table in SMEM, apply flow ============
    sbins[tid] = __ldcg(&g_bins[tid]);        // 1024 entries = TPB
    __syncthreads();

    // mask-free fast path: track running max |state|; exact redo if >= 10.
    float z0 = xa.x, z1 = xa.y, prod = 1.0f;
    float mx = fmaxf(fabsf(z0), fabsf(z1));

    #pragma unroll
    for (int s = 0; s < NBLOCKS; s++) {
        const float4* tb = sbins + (NBLOCKS - 1 - s) * BINS;
        float t2 = fmaf(z1, INV_BIN, IDX_OFF);
        int   k  = (int)(__float_as_uint(t2 + MAGIC) & 0x1Fu);
        float4 sc = tb[k];
        float p0 = fmaf(t2, sc.x, sc.y);      // shift
        float ef = fmaf(t2, sc.z, sc.w);      // exp(-scale)
        float zn = (z0 - p0) * ef;
        prod *= ef;
        mx = fmaxf(mx, fabsf(zn));
        z0 = z1; z1 = zn;
    }

    // fallback: any lane whose trajectory ever reached |z| >= 10 gets the
    // exact masked recompute (expected: no warp takes this).
    unsigned bad = __ballot_sync(0xffffffffu, !(mx < LIMIT_R));
    if (bad) {
        float w0 = xa.x, w1 = xa.y, pr = 1.0f;
        bool alive = true;
        #pragma unroll 4
        for (int s = 0; s < NBLOCKS; s++) {
            const float4* tb = sbins + (NBLOCKS - 1 - s) * BINS;
            alive = alive && (fmaxf(fabsf(w0), fabsf(w1)) < LIMIT_R);
            float t2 = fmaf(w1, INV_BIN, IDX_OFF);
            int   k  = (int)(__float_as_uint(t2 + MAGIC) & 0x1Fu);
            float4 sc = tb[k];
            float p0 = fmaf(t2, sc.x, sc.y);
            float ef = fmaf(t2, sc.z, sc.w);
            float zn = (w0 - p0) * ef;
            float n0 = w1;
            float n1 = alive ? zn : w0;       // dead: label-swap only
            pr *= alive ? ef : 1.0f;
            w0 = n0; w1 = n1;
        }
        bool mybad = !(mx < LIMIT_R);
        z0   = mybad ? w0 : z0;
        z1   = mybad ? w1 : z1;
        prod = mybad ? pr : prod;
    }

    const float e0 = __expf(-ls0), e1 = __expf(-ls1);
    const float cbase = -1.8378770664093454836f - (ls0 + ls1);

    float t0 = (z0 - loc0) * e0, t1 = (z1 - loc1) * e1;
    float va = cbase - 0.5f * (t0 * t0 + t1 * t1) + __logf(prod);

    // ---- CTA reduction: warp shfl trees (deterministic fixed order) ----
    float wsum = warp_sum(va);
    __syncthreads();                        // done reading sbins (safety)
    if (lane == 0) swarp[wid] = wsum;
    __syncthreads();
    if (wid == 0) {
        float v = swarp[lane];
        v = warp_sum(v);
        if (lane == 0) {
            g_partials[cta] = v;
            __threadfence();
            unsigned int c = atomicAdd(&g_count, 1u);
            isLast = (c == NCTA - 1);
        }
    }
    __syncthreads();

    // last CTA, warp 0: fixed-order double final reduction
    if (isLast && wid == 0) {
        double s = (double)g_partials[lane]
                 + (double)g_partials[lane + 32]
                 + (double)g_partials[lane + 64]
                 + (double)g_partials[lane + 96];
        #pragma unroll
        for (int off = 16; off > 0; off >>= 1)
            s += __shfl_xor_sync(0xffffffffu, s, off);
        if (lane == 0) {
            out[0] = (float)s;
            g_count = 0u;                   // reset for next replay
            g_build_done = 0u;
        }
    }
}

extern "C" void kernel_launch(void* const* d_in, const int* in_sizes, int n_in,
                              void* d_out, int out_size)
{
    const float* x    = (const float*)d_in[0];
    const float* W1   = (const float*)d_in[1];
    const float* b1   = (const float*)d_in[2];
    const float* W2   = (const float*)d_in[3];
    const float* b2   = (const float*)d_in[4];
    const float* W3   = (const float*)d_in[5];
    const float* b3   = (const float*)d_in[6];
    const float* loc  = (const float*)d_in[7];
    const float* logs = (const float*)d_in[8];

    realnvp_fused<<<NCTA, TPB, SMEM_BYTES>>>(x, W1, b1, W2, b2, W3, b3,
                                             loc, logs, (float*)d_out);
}